// round 10
// baseline (speedup 1.0000x reference)
#include <cuda_runtime.h>
#include <cuda_bf16.h>
#include <cstdint>
#include <cstddef>

// ---------------------------------------------------------------------------
// LiquidNeuralNetwork (CfC / AutoNCP) — R10 (= R9 resubmit after infra failure)
//  * ta/tb gates merged -> 3 gate matrices
//  * input-part GEMM: BM=BN=128, BK=16, 8x8 microtile, f32x2 packed FMA
//    (2 B SMEM per FFMA2 — was 3 B in R6; L1 was 94.9% saturated)
//  * recurrent pass unchanged from R6 (hybrid register/SMEM weights)
// ---------------------------------------------------------------------------

typedef unsigned long long ull;

#define TSTEPS 1024
#define NBATCH 256
#define MROWS  (NBATCH * TSTEPS)

// layer dims
#define U0 135
#define FIN0 128
#define NG0 405
#define NGP0 408
#define UP0 136

#define U1 89
#define FIN1 135
#define NG1 267
#define NGP1 272
#define UP1 96

#define U2 32
#define FIN2 89
#define NG2 96
#define NGP2 96
#define UP2 32

// ---------------- f32x2 helpers (ptxas won't auto-fuse; inline PTX) --------
__device__ __forceinline__ ull ffma2(ull a, ull b, ull c) {
    ull d; asm("fma.rn.f32x2 %0, %1, %2, %3;" : "=l"(d) : "l"(a), "l"(b), "l"(c));
    return d;
}
__device__ __forceinline__ ull fadd2(ull a, ull b) {
    ull d; asm("add.rn.f32x2 %0, %1, %2;" : "=l"(d) : "l"(a), "l"(b));
    return d;
}
__device__ __forceinline__ ull fdup(float x) {
    ull d; asm("mov.b64 %0, {%1, %1};" : "=l"(d) : "f"(x));
    return d;
}
__device__ __forceinline__ ull fpack(float lo, float hi) {
    ull d; asm("mov.b64 %0, {%1, %2};" : "=l"(d) : "f"(lo), "f"(hi));
    return d;
}
__device__ __forceinline__ float2 funpack(ull v) {
    float2 f; asm("mov.b64 {%0, %1}, %2;" : "=f"(f.x), "=f"(f.y) : "l"(v));
    return f;
}

// ---------------- scratch (device globals; zero-initialized) ---------------
__device__ float g_G0[(size_t)MROWS * NGP0];
__device__ float g_H0[(size_t)MROWS * UP0];
__device__ float g_G1[(size_t)MROWS * NGP1];
__device__ float g_H1[(size_t)MROWS * UP1];
__device__ float g_G2[(size_t)MROWS * NGP2];
__device__ float g_H2[(size_t)MROWS * UP2];

__device__ float g_Wx0[FIN0 * NGP0];
__device__ float g_Wh0[UP0 * NGP0];
__device__ float g_b0[NGP0];
__device__ float g_Wx1[FIN1 * NGP1];
__device__ float g_Wh1[UP1 * NGP1];
__device__ float g_b1[NGP1];
__device__ float g_Wx2[FIN2 * NGP2];
__device__ float g_Wh2[UP2 * NGP2];
__device__ float g_b2[NGP2];
__device__ float g_fcwT[32 * 32];

// ---------------------------------------------------------------------------
// Fused weight prep: all 3 layers + fc transpose in one kernel.
// Gate order n: [0,U)=ff1, [U,2U)=ff2, [2U,3U)=s(=ta+tb merged).
// ---------------------------------------------------------------------------
__device__ __forceinline__ void prep_dev(
    int U, int FIN, int NG, int NGP, int UP,
    const float* __restrict__ ff1w, const float* __restrict__ ff1b,
    const float* __restrict__ ff2w, const float* __restrict__ ff2b,
    const float* __restrict__ taw,  const float* __restrict__ tab,
    const float* __restrict__ tbw,  const float* __restrict__ tbb,
    const int*   __restrict__ mask,
    float* __restrict__ Wx, float* __restrict__ Wh, float* __restrict__ bias,
    int g0, int stride)
{
    const int C = FIN + U;
    for (int i = g0; i < FIN * NGP; i += stride) {
        int k = i / NGP, n = i % NGP;
        float v = 0.f;
        if (n < U)          v = ff1w[n * C + k] * (float)mask[n * C + k];
        else if (n < 2 * U) v = ff2w[(n - U) * C + k] * (float)mask[(n - U) * C + k];
        else if (n < NG)    v = taw[(n - 2 * U) * C + k] + tbw[(n - 2 * U) * C + k];
        Wx[i] = v;
    }
    for (int i = g0; i < UP * NGP; i += stride) {
        int k = i / NGP, n = i % NGP;
        float v = 0.f;
        if (k < U) {   // recurrent block of the NCP mask is all-ones
            if (n < U)          v = ff1w[n * C + FIN + k];
            else if (n < 2 * U) v = ff2w[(n - U) * C + FIN + k];
            else if (n < NG)    v = taw[(n - 2 * U) * C + FIN + k] + tbw[(n - 2 * U) * C + FIN + k];
        }
        Wh[i] = v;
    }
    for (int i = g0; i < NGP; i += stride) {
        float v = 0.f;
        if (i < U)          v = ff1b[i];
        else if (i < 2 * U) v = ff2b[i - U];
        else if (i < NG)    v = tab[i - 2 * U] + tbb[i - 2 * U];
        bias[i] = v;
    }
}

__global__ void prep_all(
    const float* f1w0, const float* f1b0, const float* f2w0, const float* f2b0,
    const float* taw0, const float* tab0, const float* tbw0, const float* tbb0,
    const int* m0,
    const float* f1w1, const float* f1b1, const float* f2w1, const float* f2b1,
    const float* taw1, const float* tab1, const float* tbw1, const float* tbb1,
    const int* m1,
    const float* f1w2, const float* f1b2, const float* f2w2, const float* f2b2,
    const float* taw2, const float* tab2, const float* tbw2, const float* tbb2,
    const int* m2,
    const float* fcw,
    float* Wx0, float* Wh0, float* B0,
    float* Wx1, float* Wh1, float* B1,
    float* Wx2, float* Wh2, float* B2,
    float* fcT)
{
    int g0 = blockIdx.x * blockDim.x + threadIdx.x;
    int st = gridDim.x * blockDim.x;
    prep_dev(U0, FIN0, NG0, NGP0, UP0, f1w0, f1b0, f2w0, f2b0, taw0, tab0, tbw0, tbb0,
             m0, Wx0, Wh0, B0, g0, st);
    prep_dev(U1, FIN1, NG1, NGP1, UP1, f1w1, f1b1, f2w1, f2b1, taw1, tab1, tbw1, tbb1,
             m1, Wx1, Wh1, B1, g0, st);
    prep_dev(U2, FIN2, NG2, NGP2, UP2, f1w2, f1b2, f2w2, f2b2, taw2, tab2, tbw2, tbb2,
             m2, Wx2, Wh2, B2, g0, st);
    if (g0 < 1024) {
        int o = g0 >> 5, k = g0 & 31;
        fcT[k * 32 + o] = fcw[o * 32 + k];
    }
}

// ---------------------------------------------------------------------------
// GEMM + bias, f32x2, high arithmetic intensity.
// BM=BN=128, BK=16, 256 threads, 8m x 8n per-thread microtile.
// Per kk: 4 x LDS.128 (64 B) -> 32 FFMA2  (2 B/FFMA2).
// Requirements: M % 128 == 0, N % 4 == 0 (guarded tails for N and K).
// ---------------------------------------------------------------------------
__global__ __launch_bounds__(256, 2)
void gemm_bias3(const float* __restrict__ A, int lda,
                const float* __restrict__ Bt, int ldb,
                const float* __restrict__ bias,
                float* __restrict__ C, int ldc,
                int N, int K) {
    __shared__ float sA[16][128];   // [k][m]
    __shared__ float sB[16][128];   // [k][n]
    const int bm = blockIdx.y * 128;
    const int bn = blockIdx.x * 128;
    const int tid = threadIdx.x;
    const int tm = (tid >> 4) << 3;   // 0..120
    const int tn = (tid & 15) << 3;   // 0..120

    ull acc[8][4];
#pragma unroll
    for (int r = 0; r < 8; ++r)
#pragma unroll
        for (int p = 0; p < 4; ++p) acc[r][p] = 0ull;

    for (int k0 = 0; k0 < K; k0 += 16) {
        // ---- stage A (transposed, conflict-free consecutive-m stores) ----
#pragma unroll
        for (int i = 0; i < 2; ++i) {
            int e = tid + i * 256;           // 0..511
            int m = e & 127;
            int k4 = (e >> 7) << 2;          // 0,4,8,12
            const float* src = A + (size_t)(bm + m) * lda + k0 + k4;
            float4 v;
            if (k0 + k4 + 3 < K) {
                v = *(const float4*)src;
            } else {
                v.x = (k0 + k4     < K) ? src[0] : 0.f;
                v.y = (k0 + k4 + 1 < K) ? src[1] : 0.f;
                v.z = (k0 + k4 + 2 < K) ? src[2] : 0.f;
                v.w = (k0 + k4 + 3 < K) ? src[3] : 0.f;
            }
            sA[k4 + 0][m] = v.x;
            sA[k4 + 1][m] = v.y;
            sA[k4 + 2][m] = v.z;
            sA[k4 + 3][m] = v.w;
        }
        // ---- stage B (row-linear, STS.128) ----
#pragma unroll
        for (int i = 0; i < 2; ++i) {
            int e = tid + i * 256;
            int kk = e >> 5;                 // 0..15
            int n4 = (e & 31) << 2;          // 0..124
            float4 v = make_float4(0.f, 0.f, 0.f, 0.f);
            if (k0 + kk < K && bn + n4 < N)  // N % 4 == 0 -> full float4 valid
                v = *(const float4*)&Bt[(size_t)(k0 + kk) * ldb + bn + n4];
            *(float4*)&sB[kk][n4] = v;
        }
        __syncthreads();
#pragma unroll
        for (int kk = 0; kk < 16; ++kk) {
            float4 a0 = *(const float4*)&sA[kk][tm];
            float4 a1 = *(const float4*)&sA[kk][tm + 4];
            ulonglong2 b0 = *(const ulonglong2*)&sB[kk][tn];
            ulonglong2 b1 = *(const ulonglong2*)&sB[kk][tn + 4];
            ull bb[4] = {b0.x, b0.y, b1.x, b1.y};
            ull d[8];
            d[0] = fdup(a0.x); d[1] = fdup(a0.y);
            d[2] = fdup(a0.z); d[3] = fdup(a0.w);
            d[4] = fdup(a1.x); d[5] = fdup(a1.y);
            d[6] = fdup(a1.z); d[7] = fdup(a1.w);
#pragma unroll
            for (int r = 0; r < 8; ++r)
#pragma unroll
                for (int p = 0; p < 4; ++p)
                    acc[r][p] = ffma2(d[r], bb[p], acc[r][p]);
        }
        __syncthreads();
    }
#pragma unroll
    for (int r = 0; r < 8; ++r) {
        float* crow = C + (size_t)(bm + tm + r) * ldc + bn + tn;
#pragma unroll
        for (int p = 0; p < 4; ++p) {
            int n = bn + tn + 2 * p;
            if (n < N) {                      // N even -> pair fully valid
                float2 f = funpack(acc[r][p]);
                f.x += bias[n];
                f.y += bias[n + 1];
                *(float2*)(crow + 2 * p) = f;
            }
        }
    }
}

// ---------------------------------------------------------------------------
// Recurrent pass, hybrid register/SMEM weights (unchanged from R6/R8 pass).
// ---------------------------------------------------------------------------
template<int U, int UP, int NGP, int TN, int NSPLIT, int KR, int THREADS>
__global__ __launch_bounds__(THREADS, 1)
void rec_hyb(const float* __restrict__ G, const float* __restrict__ Wg,
             float* __restrict__ H) {
    constexpr int NP = TN / 2;
    constexpr int P = NGP / TN;
    constexpr int KH = UP / NSPLIT;
    constexpr int KS = KH - KR;
    constexpr int MT = P * NSPLIT;
    constexpr int ROWU = KS * NP + 2;
    constexpr int REDN = (NSPLIT > 1) ? (NSPLIT - 1) * P * 2 * NP : 0;

    extern __shared__ __align__(16) unsigned char dynsmem[];
    ull* sW   = (ull*)dynsmem;
    ull* shd  = sW + (size_t)MT * ROWU;
    ull* sred = shd + 2 * UP;
    float* sg = (float*)(sred + REDN);

    const int tid = threadIdx.x;
    const bool mv = tid < MT;
    const int s = mv ? (tid / P) : 0;
    const int cg = tid % P;
    const int n0 = cg * TN;
    const int kbase = s * KH;
    const bool lead = tid < P;

    ull w[KR * NP];
#pragma unroll
    for (int j = 0; j < KR; ++j)
#pragma unroll
        for (int p = 0; p < NP; ++p) {
            float2 wv = *(const float2*)&Wg[(size_t)(kbase + j) * NGP + n0 + 2 * p];
            w[j * NP + p] = fpack(wv.x, wv.y);
        }
    ull* wsp = sW + (size_t)tid * ROWU;
    if (mv) {
#pragma unroll
        for (int j = 0; j < KS; ++j)
#pragma unroll
            for (int p = 0; p < NP; ++p) {
                float2 wv = *(const float2*)&Wg[(size_t)(kbase + KR + j) * NGP + n0 + 2 * p];
                wsp[j * NP + p] = fpack(wv.x, wv.y);
            }
    }
    for (int i = tid; i < 2 * UP; i += THREADS) shd[i] = 0ull;
    __syncthreads();

    const size_t bb0 = (size_t)blockIdx.x * 2;
    const float* Gp = G + bb0 * TSTEPS * NGP + n0;
    const size_t GOFF = (size_t)TSTEPS * NGP;
    float* Hp = H + bb0 * TSTEPS * UP;

    for (int t = 0; t < TSTEPS; ++t) {
        float gav[TN], gbv[TN];
        if (lead) {
            if constexpr (TN == 4) {
                float4 a = *(const float4*)Gp;
                float4 b = *(const float4*)(Gp + GOFF);
                gav[0] = a.x; gav[1] = a.y; gav[2] = a.z; gav[3] = a.w;
                gbv[0] = b.x; gbv[1] = b.y; gbv[2] = b.z; gbv[3] = b.w;
            } else {
                float2 a = *(const float2*)Gp;
                float2 b = *(const float2*)(Gp + GOFF);
                gav[0] = a.x; gav[1] = a.y;
                gbv[0] = b.x; gbv[1] = b.y;
            }
        }

        ull acc[2][NP][2];
#pragma unroll
        for (int b = 0; b < 2; ++b)
#pragma unroll
            for (int p = 0; p < NP; ++p) { acc[b][p][0] = 0ull; acc[b][p][1] = 0ull; }

        if (mv) {
#pragma unroll
            for (int j = 0; j < KR; j += 2) {
                ulonglong2 h0 = *(const ulonglong2*)&shd[0 * UP + kbase + j];
                ulonglong2 h1 = *(const ulonglong2*)&shd[1 * UP + kbase + j];
#pragma unroll
                for (int p = 0; p < NP; ++p) {
                    acc[0][p][0] = ffma2(w[j * NP + p],       h0.x, acc[0][p][0]);
                    acc[0][p][1] = ffma2(w[(j + 1) * NP + p], h0.y, acc[0][p][1]);
                    acc[1][p][0] = ffma2(w[j * NP + p],       h1.x, acc[1][p][0]);
                    acc[1][p][1] = ffma2(w[(j + 1) * NP + p], h1.y, acc[1][p][1]);
                }
            }
#pragma unroll
            for (int j = 0; j < KS; j += 2) {
                ulonglong2 h0 = *(const ulonglong2*)&shd[0 * UP + kbase + KR + j];
                ulonglong2 h1 = *(const ulonglong2*)&shd[1 * UP + kbase + KR + j];
#pragma unroll
                for (int p = 0; p < NP; ++p) {
                    ull wa = wsp[j * NP + p];
                    ull wb = wsp[(j + 1) * NP + p];
                    acc[0][p][0] = ffma2(wa, h0.x, acc[0][p][0]);
                    acc[0][p][1] = ffma2(wb, h0.y, acc[0][p][1]);
                    acc[1][p][0] = ffma2(wa, h1.x, acc[1][p][0]);
                    acc[1][p][1] = ffma2(wb, h1.y, acc[1][p][1]);
                }
            }
            if (s > 0) {
#pragma unroll
                for (int b = 0; b < 2; ++b)
#pragma unroll
                    for (int p = 0; p < NP; ++p)
                        sred[((s - 1) * P + cg) * 2 * NP + b * NP + p] =
                            fadd2(acc[b][p][0], acc[b][p][1]);
            }
        }
        __syncthreads();
        if (lead) {
#pragma unroll
            for (int b = 0; b < 2; ++b)
#pragma unroll
                for (int p = 0; p < NP; ++p) {
                    ull v = fadd2(acc[b][p][0], acc[b][p][1]);
#pragma unroll
                    for (int s2 = 1; s2 < NSPLIT; ++s2)
                        v = fadd2(v, sred[((s2 - 1) * P + cg) * 2 * NP + b * NP + p]);
                    float2 f = funpack(v);
                    float ge = b ? gbv[2 * p] : gav[2 * p];
                    float go = b ? gbv[2 * p + 1] : gav[2 * p + 1];
                    sg[b * NGP + n0 + 2 * p]     = f.x + ge;
                    sg[b * NGP + n0 + 2 * p + 1] = f.y + go;
                }
        }
        __syncthreads();
        for (int i = tid; i < 2 * U; i += THREADS) {
            int bb = (i >= U) ? 1 : 0;
            int u = i - bb * U;
            float f1 = tanhf(sg[bb * NGP + u]);
            float f2 = tanhf(sg[bb * NGP + u + U]);
            float sv = sg[bb * NGP + u + 2 * U];
            float sig = 1.f / (1.f + __expf(-sv));
            float hn = f1 + sig * (f2 - f1);
            Hp[((size_t)bb * TSTEPS + t) * UP + u] = hn;
            shd[bb * UP + u] = fdup(hn);
        }
        __syncthreads();
        Gp += NGP;
    }
}

// rec configs (unchanged)
#define R0_TN 4
#define R0_NS 2
#define R0_KR 40
#define R0_TH 256
#define R1_TN 2
#define R1_NS 2
#define R1_KR 48
#define R1_TH 288
#define R2_TN 2
#define R2_NS 1
#define R2_KR 32
#define R2_TH 96

static size_t rec_sm(int NGP, int UP, int TN, int NSPLIT, int KR) {
    int NP = TN / 2, P = NGP / TN;
    int KH = UP / NSPLIT, KS = KH - KR;
    int MT = P * NSPLIT;
    size_t rowu = (size_t)KS * NP + 2;
    size_t red = (NSPLIT > 1) ? (size_t)(NSPLIT - 1) * P * 2 * NP : 0;
    return ((size_t)MT * rowu + 2 * (size_t)UP + red) * 8 + (size_t)2 * NGP * 4;
}

// ---------------------------------------------------------------------------
// host side
// ---------------------------------------------------------------------------
static float* dev_addr(const void* sym) {
    void* p = nullptr;
    cudaGetSymbolAddress(&p, sym);
    return (float*)p;
}

extern "C" void kernel_launch(void* const* d_in, const int* in_sizes, int n_in,
                              void* d_out, int out_size) {
    // Resolve input ordering: dict order has mask0 (35505 ints) at index 9,
    // signature order has l1_ff1_w (19936 floats) there.
    int L0 = 1, M0, L1, M1, L2, M2, FCW, FCB;
    if (in_sizes[9] == 19936) {            // signature order
        L1 = 9; L2 = 17; FCW = 25; FCB = 26; M0 = 27; M1 = 28; M2 = 29;
    } else {                               // dict order
        M0 = 9; L1 = 10; M1 = 18; L2 = 19; M2 = 27; FCW = 28; FCB = 29;
    }

    const float* X = (const float*)d_in[0];
    float* OUT = (float*)d_out;

    float* G0 = dev_addr(g_G0); float* H0 = dev_addr(g_H0);
    float* G1 = dev_addr(g_G1); float* H1 = dev_addr(g_H1);
    float* G2 = dev_addr(g_G2); float* H2 = dev_addr(g_H2);
    float* Wx0 = dev_addr(g_Wx0); float* Wh0 = dev_addr(g_Wh0); float* B0 = dev_addr(g_b0);
    float* Wx1 = dev_addr(g_Wx1); float* Wh1 = dev_addr(g_Wh1); float* B1 = dev_addr(g_b1);
    float* Wx2 = dev_addr(g_Wx2); float* Wh2 = dev_addr(g_Wh2); float* B2 = dev_addr(g_b2);
    float* FcT = dev_addr(g_fcwT);

    size_t sm0 = rec_sm(NGP0, UP0, R0_TN, R0_NS, R0_KR);
    size_t sm1 = rec_sm(NGP1, UP1, R1_TN, R1_NS, R1_KR);
    size_t sm2 = rec_sm(NGP2, UP2, R2_TN, R2_NS, R2_KR);
    cudaFuncSetAttribute((const void*)rec_hyb<U0, UP0, NGP0, R0_TN, R0_NS, R0_KR, R0_TH>,
                         cudaFuncAttributeMaxDynamicSharedMemorySize, (int)sm0);
    cudaFuncSetAttribute((const void*)rec_hyb<U1, UP1, NGP1, R1_TN, R1_NS, R1_KR, R1_TH>,
                         cudaFuncAttributeMaxDynamicSharedMemorySize, (int)sm1);
    cudaFuncSetAttribute((const void*)rec_hyb<U2, UP2, NGP2, R2_TN, R2_NS, R2_KR, R2_TH>,
                         cudaFuncAttributeMaxDynamicSharedMemorySize, (int)sm2);

    // ---- fused weight prep (1 launch) ----
    prep_all<<<512, 256>>>(
        (const float*)d_in[L0 + 0], (const float*)d_in[L0 + 1],
        (const float*)d_in[L0 + 2], (const float*)d_in[L0 + 3],
        (const float*)d_in[L0 + 4], (const float*)d_in[L0 + 5],
        (const float*)d_in[L0 + 6], (const float*)d_in[L0 + 7],
        (const int*)d_in[M0],
        (const float*)d_in[L1 + 0], (const float*)d_in[L1 + 1],
        (const float*)d_in[L1 + 2], (const float*)d_in[L1 + 3],
        (const float*)d_in[L1 + 4], (const float*)d_in[L1 + 5],
        (const float*)d_in[L1 + 6], (const float*)d_in[L1 + 7],
        (const int*)d_in[M1],
        (const float*)d_in[L2 + 0], (const float*)d_in[L2 + 1],
        (const float*)d_in[L2 + 2], (const float*)d_in[L2 + 3],
        (const float*)d_in[L2 + 4], (const float*)d_in[L2 + 5],
        (const float*)d_in[L2 + 6], (const float*)d_in[L2 + 7],
        (const int*)d_in[M2],
        (const float*)d_in[FCW],
        Wx0, Wh0, B0, Wx1, Wh1, B1, Wx2, Wh2, B2, FcT);

    const int MBB = MROWS / 128;   // 2048

    // ---- layer 0 ----
    gemm_bias3<<<dim3((NGP0 + 127) / 128, MBB), 256>>>(X, FIN0, Wx0, NGP0, B0, G0, NGP0, NGP0, FIN0);
    rec_hyb<U0, UP0, NGP0, R0_TN, R0_NS, R0_KR, R0_TH>
        <<<NBATCH / 2, R0_TH, sm0>>>(G0, Wh0, H0);
    // ---- layer 1 ----
    gemm_bias3<<<dim3((NGP1 + 127) / 128, MBB), 256>>>(H0, UP0, Wx1, NGP1, B1, G1, NGP1, NGP1, U0);
    rec_hyb<U1, UP1, NGP1, R1_TN, R1_NS, R1_KR, R1_TH>
        <<<NBATCH / 2, R1_TH, sm1>>>(G1, Wh1, H1);
    // ---- layer 2 ----
    gemm_bias3<<<dim3((NGP2 + 127) / 128, MBB), 256>>>(H1, UP1, Wx2, NGP2, B2, G2, NGP2, NGP2, U1);
    rec_hyb<U2, UP2, NGP2, R2_TN, R2_NS, R2_KR, R2_TH>
        <<<NBATCH / 2, R2_TH, sm2>>>(G2, Wh2, H2);
    // ---- final FC (adaptive pool is identity since MOT == OUT) ----
    gemm_bias3<<<dim3(1, MBB), 256>>>(H2, UP2, FcT, 32, (const float*)d_in[FCB], OUT, 32, 32, 32);
}

// round 11
// speedup vs baseline: 1.4715x; 1.4715x over previous
#include <cuda_runtime.h>
#include <cuda_bf16.h>
#include <cstdint>
#include <cstddef>

// ---------------------------------------------------------------------------
// LiquidNeuralNetwork (CfC / AutoNCP) — R11
//  * GEMM: reverted to the measured-good gemm_bias2 (R8, 5418us total)
//  * rec:  rewritten rec_hyb2 — transposed SMEM weights (conflict-free),
//          2 barriers/step instead of 3, no serial lead phase,
//          G loads moved to activation threads (coalesced, issued early)
// ---------------------------------------------------------------------------

typedef unsigned long long ull;

#define TSTEPS 1024
#define NBATCH 256
#define MROWS  (NBATCH * TSTEPS)

// layer dims
#define U0 135
#define FIN0 128
#define NG0 405
#define NGP0 408
#define UP0 136

#define U1 89
#define FIN1 135
#define NG1 267
#define NGP1 272
#define UP1 96

#define U2 32
#define FIN2 89
#define NG2 96
#define NGP2 96
#define UP2 32

// ---------------- f32x2 helpers (ptxas won't auto-fuse; inline PTX) --------
__device__ __forceinline__ ull ffma2(ull a, ull b, ull c) {
    ull d; asm("fma.rn.f32x2 %0, %1, %2, %3;" : "=l"(d) : "l"(a), "l"(b), "l"(c));
    return d;
}
__device__ __forceinline__ ull fadd2(ull a, ull b) {
    ull d; asm("add.rn.f32x2 %0, %1, %2;" : "=l"(d) : "l"(a), "l"(b));
    return d;
}
__device__ __forceinline__ ull fdup(float x) {
    ull d; asm("mov.b64 %0, {%1, %1};" : "=l"(d) : "f"(x));
    return d;
}
__device__ __forceinline__ ull fpack(float lo, float hi) {
    ull d; asm("mov.b64 %0, {%1, %2};" : "=l"(d) : "f"(lo), "f"(hi));
    return d;
}
__device__ __forceinline__ float2 funpack(ull v) {
    float2 f; asm("mov.b64 {%0, %1}, %2;" : "=f"(f.x), "=f"(f.y) : "l"(v));
    return f;
}

// ---------------- scratch (device globals; zero-initialized) ---------------
__device__ float g_G0[(size_t)MROWS * NGP0];
__device__ float g_H0[(size_t)MROWS * UP0];
__device__ float g_G1[(size_t)MROWS * NGP1];
__device__ float g_H1[(size_t)MROWS * UP1];
__device__ float g_G2[(size_t)MROWS * NGP2];
__device__ float g_H2[(size_t)MROWS * UP2];

__device__ float g_Wx0[FIN0 * NGP0];
__device__ float g_Wh0[UP0 * NGP0];
__device__ float g_b0[NGP0];
__device__ float g_Wx1[FIN1 * NGP1];
__device__ float g_Wh1[UP1 * NGP1];
__device__ float g_b1[NGP1];
__device__ float g_Wx2[FIN2 * NGP2];
__device__ float g_Wh2[UP2 * NGP2];
__device__ float g_b2[NGP2];
__device__ float g_fcwT[32 * 32];

// ---------------------------------------------------------------------------
// Fused weight prep: all 3 layers + fc transpose in one kernel.
// Gate order n: [0,U)=ff1, [U,2U)=ff2, [2U,3U)=s(=ta+tb merged).
// ---------------------------------------------------------------------------
__device__ __forceinline__ void prep_dev(
    int U, int FIN, int NG, int NGP, int UP,
    const float* __restrict__ ff1w, const float* __restrict__ ff1b,
    const float* __restrict__ ff2w, const float* __restrict__ ff2b,
    const float* __restrict__ taw,  const float* __restrict__ tab,
    const float* __restrict__ tbw,  const float* __restrict__ tbb,
    const int*   __restrict__ mask,
    float* __restrict__ Wx, float* __restrict__ Wh, float* __restrict__ bias,
    int g0, int stride)
{
    const int C = FIN + U;
    for (int i = g0; i < FIN * NGP; i += stride) {
        int k = i / NGP, n = i % NGP;
        float v = 0.f;
        if (n < U)          v = ff1w[n * C + k] * (float)mask[n * C + k];
        else if (n < 2 * U) v = ff2w[(n - U) * C + k] * (float)mask[(n - U) * C + k];
        else if (n < NG)    v = taw[(n - 2 * U) * C + k] + tbw[(n - 2 * U) * C + k];
        Wx[i] = v;
    }
    for (int i = g0; i < UP * NGP; i += stride) {
        int k = i / NGP, n = i % NGP;
        float v = 0.f;
        if (k < U) {   // recurrent block of the NCP mask is all-ones
            if (n < U)          v = ff1w[n * C + FIN + k];
            else if (n < 2 * U) v = ff2w[(n - U) * C + FIN + k];
            else if (n < NG)    v = taw[(n - 2 * U) * C + FIN + k] + tbw[(n - 2 * U) * C + FIN + k];
        }
        Wh[i] = v;
    }
    for (int i = g0; i < NGP; i += stride) {
        float v = 0.f;
        if (i < U)          v = ff1b[i];
        else if (i < 2 * U) v = ff2b[i - U];
        else if (i < NG)    v = tab[i - 2 * U] + tbb[i - 2 * U];
        bias[i] = v;
    }
}

__global__ void prep_all(
    const float* f1w0, const float* f1b0, const float* f2w0, const float* f2b0,
    const float* taw0, const float* tab0, const float* tbw0, const float* tbb0,
    const int* m0,
    const float* f1w1, const float* f1b1, const float* f2w1, const float* f2b1,
    const float* taw1, const float* tab1, const float* tbw1, const float* tbb1,
    const int* m1,
    const float* f1w2, const float* f1b2, const float* f2w2, const float* f2b2,
    const float* taw2, const float* tab2, const float* tbw2, const float* tbb2,
    const int* m2,
    const float* fcw,
    float* Wx0, float* Wh0, float* B0,
    float* Wx1, float* Wh1, float* B1,
    float* Wx2, float* Wh2, float* B2,
    float* fcT)
{
    int g0 = blockIdx.x * blockDim.x + threadIdx.x;
    int st = gridDim.x * blockDim.x;
    prep_dev(U0, FIN0, NG0, NGP0, UP0, f1w0, f1b0, f2w0, f2b0, taw0, tab0, tbw0, tbb0,
             m0, Wx0, Wh0, B0, g0, st);
    prep_dev(U1, FIN1, NG1, NGP1, UP1, f1w1, f1b1, f2w1, f2b1, taw1, tab1, tbw1, tbb1,
             m1, Wx1, Wh1, B1, g0, st);
    prep_dev(U2, FIN2, NG2, NGP2, UP2, f1w2, f1b2, f2w2, f2b2, taw2, tab2, tbw2, tbb2,
             m2, Wx2, Wh2, B2, g0, st);
    if (g0 < 1024) {
        int o = g0 >> 5, k = g0 & 31;
        fcT[k * 32 + o] = fcw[o * 32 + k];
    }
}

// ---------------------------------------------------------------------------
// GEMM + bias (R8 measured-good version). BM=BN=64, BK=32, 128 threads,
// per-thread tile 4m x 8n, f32x2 packed FMA.
// ---------------------------------------------------------------------------
__global__ __launch_bounds__(128)
void gemm_bias2(const float* __restrict__ A, int lda,
                const float* __restrict__ Bt, int ldb,
                const float* __restrict__ bias,
                float* __restrict__ C, int ldc,
                int N, int K) {
    __shared__ float sA[32][68];
    __shared__ float sB[32][68];
    const int bm = blockIdx.y * 64;
    const int bn = blockIdx.x * 64;
    const int tid = threadIdx.x;
    const int tm = (tid >> 3) << 2;
    const int tn = (tid & 7) << 3;
    ull acc[4][4];
#pragma unroll
    for (int i = 0; i < 4; ++i)
#pragma unroll
        for (int p = 0; p < 4; ++p) acc[i][p] = 0ull;

    for (int k0 = 0; k0 < K; k0 += 32) {
#pragma unroll
        for (int i = 0; i < 4; ++i) {
            int e = tid + i * 128;
            int m = e >> 3, k4 = (e & 7) << 2;
            const float* src = A + (size_t)(bm + m) * lda + k0 + k4;
            float4 v;
            if (k0 + k4 + 3 < K) {
                v = *(const float4*)src;
            } else {
                v.x = (k0 + k4     < K) ? src[0] : 0.f;
                v.y = (k0 + k4 + 1 < K) ? src[1] : 0.f;
                v.z = (k0 + k4 + 2 < K) ? src[2] : 0.f;
                v.w = 0.f;
            }
            sA[k4 + 0][m] = v.x; sA[k4 + 1][m] = v.y;
            sA[k4 + 2][m] = v.z; sA[k4 + 3][m] = v.w;
        }
#pragma unroll
        for (int i = 0; i < 4; ++i) {
            int e = tid + i * 128;
            int kk = e >> 4, n4 = (e & 15) << 2;
            float4 v = make_float4(0.f, 0.f, 0.f, 0.f);
            if (k0 + kk < K && bn + n4 < N)
                v = *(const float4*)(Bt + (size_t)(k0 + kk) * ldb + bn + n4);
            *(float4*)&sB[kk][n4] = v;
        }
        __syncthreads();
#pragma unroll
        for (int kk = 0; kk < 32; ++kk) {
            float4 a = *(const float4*)&sA[kk][tm];
            ulonglong2 bl = *(const ulonglong2*)&sB[kk][tn];
            ulonglong2 bh = *(const ulonglong2*)&sB[kk][tn + 4];
            ull d0 = fdup(a.x), d1 = fdup(a.y), d2 = fdup(a.z), d3 = fdup(a.w);
            acc[0][0] = ffma2(d0, bl.x, acc[0][0]);
            acc[1][0] = ffma2(d1, bl.x, acc[1][0]);
            acc[2][0] = ffma2(d2, bl.x, acc[2][0]);
            acc[3][0] = ffma2(d3, bl.x, acc[3][0]);
            acc[0][1] = ffma2(d0, bl.y, acc[0][1]);
            acc[1][1] = ffma2(d1, bl.y, acc[1][1]);
            acc[2][1] = ffma2(d2, bl.y, acc[2][1]);
            acc[3][1] = ffma2(d3, bl.y, acc[3][1]);
            acc[0][2] = ffma2(d0, bh.x, acc[0][2]);
            acc[1][2] = ffma2(d1, bh.x, acc[1][2]);
            acc[2][2] = ffma2(d2, bh.x, acc[2][2]);
            acc[3][2] = ffma2(d3, bh.x, acc[3][2]);
            acc[0][3] = ffma2(d0, bh.y, acc[0][3]);
            acc[1][3] = ffma2(d1, bh.y, acc[1][3]);
            acc[2][3] = ffma2(d2, bh.y, acc[2][3]);
            acc[3][3] = ffma2(d3, bh.y, acc[3][3]);
        }
        __syncthreads();
    }
#pragma unroll
    for (int i = 0; i < 4; ++i) {
        float* crow = C + (size_t)(bm + tm + i) * ldc + bn + tn;
#pragma unroll
        for (int p = 0; p < 4; ++p) {
            int n = bn + tn + 2 * p;
            if (n < N) {
                float2 f = funpack(acc[i][p]);
                f.x += bias[n];
                f.y += bias[n + 1];
                *(float2*)(crow + 2 * p) = f;
            }
        }
    }
}

// ---------------------------------------------------------------------------
// Recurrent pass v2.
//  * TN cols/thread, NSPLIT-way k-split. First KR k-slices of each group in
//    registers; remaining KS in SMEM TRANSPOSED [slice][thread] so warp
//    lanes read consecutive ulls (zero bank conflicts).
//  * Matvec threads write per-group partials to sgp; activation threads
//    combine partials + G themselves -> 2 barriers/step, no serial phase.
//  * G loads issued by activation threads at step top (coalesced), consumed
//    after the barrier -> DRAM latency hidden under matvec issue.
// ---------------------------------------------------------------------------
template<int U, int UP, int NGP, int TN, int NSPLIT, int KR, int THREADS>
__global__ __launch_bounds__(THREADS, 1)
void rec_hyb2(const float* __restrict__ G, const float* __restrict__ Wg,
              float* __restrict__ H) {
    constexpr int NP = TN / 2;
    constexpr int P = NGP / TN;
    constexpr int KH = UP / NSPLIT;
    constexpr int KS = KH - KR;
    constexpr int MT = P * NSPLIT;
    constexpr int SWN = KS * NP * MT;            // transposed smem weights
    constexpr int NACT = (2 * U + THREADS - 1) / THREADS;

    extern __shared__ __align__(16) unsigned char dynsmem[];
    ull* sW   = (ull*)dynsmem;                   // [KS*NP][MT]
    ull* shd  = sW + SWN;                        // [2][UP] dup'd h
    float* sgp = (float*)(shd + 2 * UP);         // [NSPLIT][2][NGP] partials

    const int tid = threadIdx.x;
    const bool mv = tid < MT;
    const int s = mv ? (tid / P) : 0;
    const int cg = tid % P;
    const int n0 = cg * TN;
    const int kbase = s * KH;

    // register-resident weight slice
    ull w[KR * NP];
#pragma unroll
    for (int j = 0; j < KR; ++j)
#pragma unroll
        for (int p = 0; p < NP; ++p) {
            float2 wv = *(const float2*)&Wg[(size_t)(kbase + j) * NGP + n0 + 2 * p];
            w[j * NP + p] = fpack(wv.x, wv.y);
        }
    // SMEM weights, transposed layout [q = j*NP+p][thread m]
    for (int idx = tid; idx < SWN; idx += THREADS) {
        int q = idx / MT, m = idx % MT;
        int j = q / NP, p = q % NP;
        int sm = m / P, cgm = m % P;
        float2 wv = *(const float2*)&Wg[(size_t)(sm * KH + KR + j) * NGP + cgm * TN + 2 * p];
        sW[idx] = fpack(wv.x, wv.y);
    }
    for (int i = tid; i < 2 * UP; i += THREADS) shd[i] = 0ull;
    __syncthreads();

    const size_t bb0 = (size_t)blockIdx.x * 2;
    const float* Gbase = G + bb0 * TSTEPS * NGP;
    const size_t GOFF = (size_t)TSTEPS * NGP;     // batch-row stride in G
    float* Hp = H + bb0 * TSTEPS * UP;

    // activation-thread unit assignment (compile-time small count)
    int ubb[NACT], uu[NACT];
    bool uvalid[NACT];
#pragma unroll
    for (int a = 0; a < NACT; ++a) {
        int i = tid + a * THREADS;
        uvalid[a] = (i < 2 * U);
        ubb[a] = (i >= U) ? 1 : 0;
        uu[a] = i - ubb[a] * U;
    }

    for (int t = 0; t < TSTEPS; ++t) {
        // 1. early G loads (activation threads), consumed after barrier
        float g1v[NACT], g2v[NACT], gsv[NACT];
#pragma unroll
        for (int a = 0; a < NACT; ++a) {
            if (uvalid[a]) {
                const float* Gr = Gbase + (ubb[a] ? GOFF : 0) + (size_t)t * NGP;
                g1v[a] = Gr[uu[a]];
                g2v[a] = Gr[uu[a] + U];
                gsv[a] = Gr[uu[a] + 2 * U];
            }
        }
        // 2. matvec
        if (mv) {
            ull acc[2][NP][2];
#pragma unroll
            for (int b = 0; b < 2; ++b)
#pragma unroll
                for (int p = 0; p < NP; ++p) { acc[b][p][0] = 0ull; acc[b][p][1] = 0ull; }
#pragma unroll
            for (int j = 0; j < KR; j += 2) {          // register weights
                ulonglong2 h0 = *(const ulonglong2*)&shd[0 * UP + kbase + j];
                ulonglong2 h1 = *(const ulonglong2*)&shd[1 * UP + kbase + j];
#pragma unroll
                for (int p = 0; p < NP; ++p) {
                    acc[0][p][0] = ffma2(w[j * NP + p],       h0.x, acc[0][p][0]);
                    acc[0][p][1] = ffma2(w[(j + 1) * NP + p], h0.y, acc[0][p][1]);
                    acc[1][p][0] = ffma2(w[j * NP + p],       h1.x, acc[1][p][0]);
                    acc[1][p][1] = ffma2(w[(j + 1) * NP + p], h1.y, acc[1][p][1]);
                }
            }
#pragma unroll
            for (int j = 0; j < KS; j += 2) {          // SMEM weights (transposed)
                ulonglong2 h0 = *(const ulonglong2*)&shd[0 * UP + kbase + KR + j];
                ulonglong2 h1 = *(const ulonglong2*)&shd[1 * UP + kbase + KR + j];
#pragma unroll
                for (int p = 0; p < NP; ++p) {
                    ull wa = sW[((j)     * NP + p) * MT + tid];
                    ull wb = sW[((j + 1) * NP + p) * MT + tid];
                    acc[0][p][0] = ffma2(wa, h0.x, acc[0][p][0]);
                    acc[0][p][1] = ffma2(wb, h0.y, acc[0][p][1]);
                    acc[1][p][0] = ffma2(wa, h1.x, acc[1][p][0]);
                    acc[1][p][1] = ffma2(wb, h1.y, acc[1][p][1]);
                }
            }
            // store per-group partials
#pragma unroll
            for (int b = 0; b < 2; ++b)
#pragma unroll
                for (int p = 0; p < NP; ++p) {
                    float2 f = funpack(fadd2(acc[b][p][0], acc[b][p][1]));
                    *(float2*)&sgp[(s * 2 + b) * NGP + n0 + 2 * p] = f;
                }
        }
        __syncthreads();
        // 3. activation: combine partials + G, update h, store H
#pragma unroll
        for (int a = 0; a < NACT; ++a) {
            if (uvalid[a]) {
                int bb = ubb[a], u = uu[a];
                float x1 = g1v[a], x2 = g2v[a], xs = gsv[a];
#pragma unroll
                for (int s2 = 0; s2 < NSPLIT; ++s2) {
                    const float* row = &sgp[(s2 * 2 + bb) * NGP];
                    x1 += row[u];
                    x2 += row[u + U];
                    xs += row[u + 2 * U];
                }
                float f1 = tanhf(x1), f2 = tanhf(x2);
                float sig = 1.f / (1.f + __expf(-xs));
                float hn = f1 + sig * (f2 - f1);
                Hp[((size_t)bb * TSTEPS + t) * UP + u] = hn;
                shd[bb * UP + u] = fdup(hn);
            }
        }
        __syncthreads();
    }
}

// rec configs
#define R0_TN 4
#define R0_NS 2
#define R0_KR 40
#define R0_TH 256
#define R1_TN 2
#define R1_NS 2
#define R1_KR 48
#define R1_TH 288
#define R2_TN 2
#define R2_NS 1
#define R2_KR 32
#define R2_TH 96

static size_t rec_sm2(int NGP, int UP, int TN, int NSPLIT, int KR) {
    int NP = TN / 2, P = NGP / TN;
    int KH = UP / NSPLIT, KS = KH - KR;
    int MT = P * NSPLIT;
    size_t swn = (size_t)KS * NP * MT;
    return (swn + 2 * (size_t)UP) * 8 + (size_t)NSPLIT * 2 * NGP * 4;
}

// ---------------------------------------------------------------------------
// host side
// ---------------------------------------------------------------------------
static float* dev_addr(const void* sym) {
    void* p = nullptr;
    cudaGetSymbolAddress(&p, sym);
    return (float*)p;
}

extern "C" void kernel_launch(void* const* d_in, const int* in_sizes, int n_in,
                              void* d_out, int out_size) {
    // Resolve input ordering: dict order has mask0 (35505 ints) at index 9,
    // signature order has l1_ff1_w (19936 floats) there.
    int L0 = 1, M0, L1, M1, L2, M2, FCW, FCB;
    if (in_sizes[9] == 19936) {            // signature order
        L1 = 9; L2 = 17; FCW = 25; FCB = 26; M0 = 27; M1 = 28; M2 = 29;
    } else {                               // dict order
        M0 = 9; L1 = 10; M1 = 18; L2 = 19; M2 = 27; FCW = 28; FCB = 29;
    }

    const float* X = (const float*)d_in[0];
    float* OUT = (float*)d_out;

    float* G0 = dev_addr(g_G0); float* H0 = dev_addr(g_H0);
    float* G1 = dev_addr(g_G1); float* H1 = dev_addr(g_H1);
    float* G2 = dev_addr(g_G2); float* H2 = dev_addr(g_H2);
    float* Wx0 = dev_addr(g_Wx0); float* Wh0 = dev_addr(g_Wh0); float* B0 = dev_addr(g_b0);
    float* Wx1 = dev_addr(g_Wx1); float* Wh1 = dev_addr(g_Wh1); float* B1 = dev_addr(g_b1);
    float* Wx2 = dev_addr(g_Wx2); float* Wh2 = dev_addr(g_Wh2); float* B2 = dev_addr(g_b2);
    float* FcT = dev_addr(g_fcwT);

    size_t sm0 = rec_sm2(NGP0, UP0, R0_TN, R0_NS, R0_KR);
    size_t sm1 = rec_sm2(NGP1, UP1, R1_TN, R1_NS, R1_KR);
    size_t sm2 = rec_sm2(NGP2, UP2, R2_TN, R2_NS, R2_KR);
    cudaFuncSetAttribute((const void*)rec_hyb2<U0, UP0, NGP0, R0_TN, R0_NS, R0_KR, R0_TH>,
                         cudaFuncAttributeMaxDynamicSharedMemorySize, (int)sm0);
    cudaFuncSetAttribute((const void*)rec_hyb2<U1, UP1, NGP1, R1_TN, R1_NS, R1_KR, R1_TH>,
                         cudaFuncAttributeMaxDynamicSharedMemorySize, (int)sm1);
    cudaFuncSetAttribute((const void*)rec_hyb2<U2, UP2, NGP2, R2_TN, R2_NS, R2_KR, R2_TH>,
                         cudaFuncAttributeMaxDynamicSharedMemorySize, (int)sm2);

    // ---- fused weight prep (1 launch) ----
    prep_all<<<512, 256>>>(
        (const float*)d_in[L0 + 0], (const float*)d_in[L0 + 1],
        (const float*)d_in[L0 + 2], (const float*)d_in[L0 + 3],
        (const float*)d_in[L0 + 4], (const float*)d_in[L0 + 5],
        (const float*)d_in[L0 + 6], (const float*)d_in[L0 + 7],
        (const int*)d_in[M0],
        (const float*)d_in[L1 + 0], (const float*)d_in[L1 + 1],
        (const float*)d_in[L1 + 2], (const float*)d_in[L1 + 3],
        (const float*)d_in[L1 + 4], (const float*)d_in[L1 + 5],
        (const float*)d_in[L1 + 6], (const float*)d_in[L1 + 7],
        (const int*)d_in[M1],
        (const float*)d_in[L2 + 0], (const float*)d_in[L2 + 1],
        (const float*)d_in[L2 + 2], (const float*)d_in[L2 + 3],
        (const float*)d_in[L2 + 4], (const float*)d_in[L2 + 5],
        (const float*)d_in[L2 + 6], (const float*)d_in[L2 + 7],
        (const int*)d_in[M2],
        (const float*)d_in[FCW],
        Wx0, Wh0, B0, Wx1, Wh1, B1, Wx2, Wh2, B2, FcT);

    const int MB = MROWS / 64;   // 4096

    // ---- layer 0 ----
    gemm_bias2<<<dim3((NGP0 + 63) / 64, MB), 128>>>(X, FIN0, Wx0, NGP0, B0, G0, NGP0, NGP0, FIN0);
    rec_hyb2<U0, UP0, NGP0, R0_TN, R0_NS, R0_KR, R0_TH>
        <<<NBATCH / 2, R0_TH, sm0>>>(G0, Wh0, H0);
    // ---- layer 1 ----
    gemm_bias2<<<dim3((NGP1 + 63) / 64, MB), 128>>>(H0, UP0, Wx1, NGP1, B1, G1, NGP1, NGP1, U0);
    rec_hyb2<U1, UP1, NGP1, R1_TN, R1_NS, R1_KR, R1_TH>
        <<<NBATCH / 2, R1_TH, sm1>>>(G1, Wh1, H1);
    // ---- layer 2 ----
    gemm_bias2<<<dim3((NGP2 + 63) / 64, MB), 128>>>(H1, UP1, Wx2, NGP2, B2, G2, NGP2, NGP2, U1);
    rec_hyb2<U2, UP2, NGP2, R2_TN, R2_NS, R2_KR, R2_TH>
        <<<NBATCH / 2, R2_TH, sm2>>>(G2, Wh2, H2);
    // ---- final FC (adaptive pool is identity since MOT == OUT) ----
    gemm_bias2<<<dim3(1, MB), 128>>>(H2, UP2, FcT, 32, (const float*)d_in[FCB], OUT, 32, 32, 32);
}

// round 14
// speedup vs baseline: 1.7291x; 1.1750x over previous
#include <cuda_runtime.h>
#include <cuda_bf16.h>
#include <cstdint>
#include <cstddef>

// ---------------------------------------------------------------------------
// LiquidNeuralNetwork (CfC / AutoNCP) — R12
//  * GEMM: BM=128 x BN=64, BK=16, 8x8 microtile (2 B LDS-return per FFMA2,
//    the R10 pipe win) while keeping BN=64 (the R8 low-tail-waste shape).
//  * rec:  rec_hyb2 unchanged from R11 (5205us pass).
// ---------------------------------------------------------------------------

typedef unsigned long long ull;

#define TSTEPS 1024
#define NBATCH 256
#define MROWS  (NBATCH * TSTEPS)

// layer dims
#define U0 135
#define FIN0 128
#define NG0 405
#define NGP0 408
#define UP0 136

#define U1 89
#define FIN1 135
#define NG1 267
#define NGP1 272
#define UP1 96

#define U2 32
#define FIN2 89
#define NG2 96
#define NGP2 96
#define UP2 32

// ---------------- f32x2 helpers (ptxas won't auto-fuse; inline PTX) --------
__device__ __forceinline__ ull ffma2(ull a, ull b, ull c) {
    ull d; asm("fma.rn.f32x2 %0, %1, %2, %3;" : "=l"(d) : "l"(a), "l"(b), "l"(c));
    return d;
}
__device__ __forceinline__ ull fadd2(ull a, ull b) {
    ull d; asm("add.rn.f32x2 %0, %1, %2;" : "=l"(d) : "l"(a), "l"(b));
    return d;
}
__device__ __forceinline__ ull fdup(float x) {
    ull d; asm("mov.b64 %0, {%1, %1};" : "=l"(d) : "f"(x));
    return d;
}
__device__ __forceinline__ ull fpack(float lo, float hi) {
    ull d; asm("mov.b64 %0, {%1, %2};" : "=l"(d) : "f"(lo), "f"(hi));
    return d;
}
__device__ __forceinline__ float2 funpack(ull v) {
    float2 f; asm("mov.b64 {%0, %1}, %2;" : "=f"(f.x), "=f"(f.y) : "l"(v));
    return f;
}

// ---------------- scratch (device globals; zero-initialized) ---------------
__device__ float g_G0[(size_t)MROWS * NGP0];
__device__ float g_H0[(size_t)MROWS * UP0];
__device__ float g_G1[(size_t)MROWS * NGP1];
__device__ float g_H1[(size_t)MROWS * UP1];
__device__ float g_G2[(size_t)MROWS * NGP2];
__device__ float g_H2[(size_t)MROWS * UP2];

__device__ float g_Wx0[FIN0 * NGP0];
__device__ float g_Wh0[UP0 * NGP0];
__device__ float g_b0[NGP0];
__device__ float g_Wx1[FIN1 * NGP1];
__device__ float g_Wh1[UP1 * NGP1];
__device__ float g_b1[NGP1];
__device__ float g_Wx2[FIN2 * NGP2];
__device__ float g_Wh2[UP2 * NGP2];
__device__ float g_b2[NGP2];
__device__ float g_fcwT[32 * 32];

// ---------------------------------------------------------------------------
// Fused weight prep (unchanged).
// Gate order n: [0,U)=ff1, [U,2U)=ff2, [2U,3U)=s(=ta+tb merged).
// ---------------------------------------------------------------------------
__device__ __forceinline__ void prep_dev(
    int U, int FIN, int NG, int NGP, int UP,
    const float* __restrict__ ff1w, const float* __restrict__ ff1b,
    const float* __restrict__ ff2w, const float* __restrict__ ff2b,
    const float* __restrict__ taw,  const float* __restrict__ tab,
    const float* __restrict__ tbw,  const float* __restrict__ tbb,
    const int*   __restrict__ mask,
    float* __restrict__ Wx, float* __restrict__ Wh, float* __restrict__ bias,
    int g0, int stride)
{
    const int C = FIN + U;
    for (int i = g0; i < FIN * NGP; i += stride) {
        int k = i / NGP, n = i % NGP;
        float v = 0.f;
        if (n < U)          v = ff1w[n * C + k] * (float)mask[n * C + k];
        else if (n < 2 * U) v = ff2w[(n - U) * C + k] * (float)mask[(n - U) * C + k];
        else if (n < NG)    v = taw[(n - 2 * U) * C + k] + tbw[(n - 2 * U) * C + k];
        Wx[i] = v;
    }
    for (int i = g0; i < UP * NGP; i += stride) {
        int k = i / NGP, n = i % NGP;
        float v = 0.f;
        if (k < U) {   // recurrent block of the NCP mask is all-ones
            if (n < U)          v = ff1w[n * C + FIN + k];
            else if (n < 2 * U) v = ff2w[(n - U) * C + FIN + k];
            else if (n < NG)    v = taw[(n - 2 * U) * C + FIN + k] + tbw[(n - 2 * U) * C + FIN + k];
        }
        Wh[i] = v;
    }
    for (int i = g0; i < NGP; i += stride) {
        float v = 0.f;
        if (i < U)          v = ff1b[i];
        else if (i < 2 * U) v = ff2b[i - U];
        else if (i < NG)    v = tab[i - 2 * U] + tbb[i - 2 * U];
        bias[i] = v;
    }
}

__global__ void prep_all(
    const float* f1w0, const float* f1b0, const float* f2w0, const float* f2b0,
    const float* taw0, const float* tab0, const float* tbw0, const float* tbb0,
    const int* m0,
    const float* f1w1, const float* f1b1, const float* f2w1, const float* f2b1,
    const float* taw1, const float* tab1, const float* tbw1, const float* tbb1,
    const int* m1,
    const float* f1w2, const float* f1b2, const float* f2w2, const float* f2b2,
    const float* taw2, const float* tab2, const float* tbw2, const float* tbb2,
    const int* m2,
    const float* fcw,
    float* Wx0, float* Wh0, float* B0,
    float* Wx1, float* Wh1, float* B1,
    float* Wx2, float* Wh2, float* B2,
    float* fcT)
{
    int g0 = blockIdx.x * blockDim.x + threadIdx.x;
    int st = gridDim.x * blockDim.x;
    prep_dev(U0, FIN0, NG0, NGP0, UP0, f1w0, f1b0, f2w0, f2b0, taw0, tab0, tbw0, tbb0,
             m0, Wx0, Wh0, B0, g0, st);
    prep_dev(U1, FIN1, NG1, NGP1, UP1, f1w1, f1b1, f2w1, f2b1, taw1, tab1, tbw1, tbb1,
             m1, Wx1, Wh1, B1, g0, st);
    prep_dev(U2, FIN2, NG2, NGP2, UP2, f1w2, f1b2, f2w2, f2b2, taw2, tab2, tbw2, tbb2,
             m2, Wx2, Wh2, B2, g0, st);
    if (g0 < 1024) {
        int o = g0 >> 5, k = g0 & 31;
        fcT[k * 32 + o] = fcw[o * 32 + k];
    }
}

// ---------------------------------------------------------------------------
// GEMM + bias, f32x2. BM=128, BN=64, BK=16, 128 threads, 8m x 8n microtile.
// Per kk per thread: 64 B LDS-return -> 32 FFMA2 (2 B/FFMA2).
// M % 128 == 0; N % 4 == 0; K-tails guarded.
// ---------------------------------------------------------------------------
__global__ __launch_bounds__(128)
void gemm_bias4(const float* __restrict__ A, int lda,
                const float* __restrict__ Bt, int ldb,
                const float* __restrict__ bias,
                float* __restrict__ C, int ldc,
                int N, int K) {
    __shared__ float sA[16][128];   // [k][m]
    __shared__ float sB[16][64];    // [k][n]
    const int bm = blockIdx.y * 128;
    const int bn = blockIdx.x * 64;
    const int tid = threadIdx.x;
    const int tm = (tid >> 3) << 3;   // 0..120
    const int tn = (tid & 7) << 3;    // 0..56

    ull acc[8][4];
#pragma unroll
    for (int r = 0; r < 8; ++r)
#pragma unroll
        for (int p = 0; p < 4; ++p) acc[r][p] = 0ull;

    for (int k0 = 0; k0 < K; k0 += 16) {
        // ---- stage A: 128m x 16k, transposed, 4 float4 loads per thread ----
#pragma unroll
        for (int i = 0; i < 4; ++i) {
            int e = tid + i * 128;           // 0..511
            int m = e & 127;
            int k4 = (e >> 7) << 2;          // 0,4,8,12
            const float* src = A + (size_t)(bm + m) * lda + k0 + k4;
            float4 v;
            if (k0 + k4 + 3 < K) {
                v = *(const float4*)src;
            } else {
                v.x = (k0 + k4     < K) ? src[0] : 0.f;
                v.y = (k0 + k4 + 1 < K) ? src[1] : 0.f;
                v.z = (k0 + k4 + 2 < K) ? src[2] : 0.f;
                v.w = 0.f;
            }
            sA[k4 + 0][m] = v.x;
            sA[k4 + 1][m] = v.y;
            sA[k4 + 2][m] = v.z;
            sA[k4 + 3][m] = v.w;
        }
        // ---- stage B: 16k x 64n, row-linear, 2 float4 per thread ----
#pragma unroll
        for (int i = 0; i < 2; ++i) {
            int e = tid + i * 128;           // 0..255
            int kk = e >> 4;                 // 0..15
            int n4 = (e & 15) << 2;          // 0..60
            float4 v = make_float4(0.f, 0.f, 0.f, 0.f);
            if (k0 + kk < K && bn + n4 < N)  // N % 4 == 0 -> full float4 valid
                v = *(const float4*)&Bt[(size_t)(k0 + kk) * ldb + bn + n4];
            *(float4*)&sB[kk][n4] = v;
        }
        __syncthreads();
#pragma unroll
        for (int kk = 0; kk < 16; ++kk) {
            float4 a0 = *(const float4*)&sA[kk][tm];
            float4 a1 = *(const float4*)&sA[kk][tm + 4];
            ulonglong2 b0 = *(const ulonglong2*)&sB[kk][tn];
            ulonglong2 b1 = *(const ulonglong2*)&sB[kk][tn + 4];
            ull bb[4] = {b0.x, b0.y, b1.x, b1.y};
            ull d[8];
            d[0] = fdup(a0.x); d[1] = fdup(a0.y);
            d[2] = fdup(a0.z); d[3] = fdup(a0.w);
            d[4] = fdup(a1.x); d[5] = fdup(a1.y);
            d[6] = fdup(a1.z); d[7] = fdup(a1.w);
#pragma unroll
            for (int r = 0; r < 8; ++r)
#pragma unroll
                for (int p = 0; p < 4; ++p)
                    acc[r][p] = ffma2(d[r], bb[p], acc[r][p]);
        }
        __syncthreads();
    }
#pragma unroll
    for (int r = 0; r < 8; ++r) {
        float* crow = C + (size_t)(bm + tm + r) * ldc + bn + tn;
#pragma unroll
        for (int p = 0; p < 4; ++p) {
            int n = bn + tn + 2 * p;
            if (n < N) {                     // N even -> pair fully valid
                float2 f = funpack(acc[r][p]);
                f.x += bias[n];
                f.y += bias[n + 1];
                *(float2*)(crow + 2 * p) = f;
            }
        }
    }
}

// ---------------------------------------------------------------------------
// Recurrent pass v2 (unchanged from R11 5205us pass).
// ---------------------------------------------------------------------------
template<int U, int UP, int NGP, int TN, int NSPLIT, int KR, int THREADS>
__global__ __launch_bounds__(THREADS, 1)
void rec_hyb2(const float* __restrict__ G, const float* __restrict__ Wg,
              float* __restrict__ H) {
    constexpr int NP = TN / 2;
    constexpr int P = NGP / TN;
    constexpr int KH = UP / NSPLIT;
    constexpr int KS = KH - KR;
    constexpr int MT = P * NSPLIT;
    constexpr int SWN = KS * NP * MT;
    constexpr int NACT = (2 * U + THREADS - 1) / THREADS;

    extern __shared__ __align__(16) unsigned char dynsmem[];
    ull* sW   = (ull*)dynsmem;                   // [KS*NP][MT]
    ull* shd  = sW + SWN;                        // [2][UP] dup'd h
    float* sgp = (float*)(shd + 2 * UP);         // [NSPLIT][2][NGP]

    const int tid = threadIdx.x;
    const bool mv = tid < MT;
    const int s = mv ? (tid / P) : 0;
    const int cg = tid % P;
    const int n0 = cg * TN;
    const int kbase = s * KH;

    ull w[KR * NP];
#pragma unroll
    for (int j = 0; j < KR; ++j)
#pragma unroll
        for (int p = 0; p < NP; ++p) {
            float2 wv = *(const float2*)&Wg[(size_t)(kbase + j) * NGP + n0 + 2 * p];
            w[j * NP + p] = fpack(wv.x, wv.y);
        }
    for (int idx = tid; idx < SWN; idx += THREADS) {
        int q = idx / MT, m = idx % MT;
        int j = q / NP, p = q % NP;
        int sm = m / P, cgm = m % P;
        float2 wv = *(const float2*)&Wg[(size_t)(sm * KH + KR + j) * NGP + cgm * TN + 2 * p];
        sW[idx] = fpack(wv.x, wv.y);
    }
    for (int i = tid; i < 2 * UP; i += THREADS) shd[i] = 0ull;
    __syncthreads();

    const size_t bb0 = (size_t)blockIdx.x * 2;
    const float* Gbase = G + bb0 * TSTEPS * NGP;
    const size_t GOFF = (size_t)TSTEPS * NGP;
    float* Hp = H + bb0 * TSTEPS * UP;

    int ubb[NACT], uu[NACT];
    bool uvalid[NACT];
#pragma unroll
    for (int a = 0; a < NACT; ++a) {
        int i = tid + a * THREADS;
        uvalid[a] = (i < 2 * U);
        ubb[a] = (i >= U) ? 1 : 0;
        uu[a] = i - ubb[a] * U;
    }

    for (int t = 0; t < TSTEPS; ++t) {
        float g1v[NACT], g2v[NACT], gsv[NACT];
#pragma unroll
        for (int a = 0; a < NACT; ++a) {
            if (uvalid[a]) {
                const float* Gr = Gbase + (ubb[a] ? GOFF : 0) + (size_t)t * NGP;
                g1v[a] = Gr[uu[a]];
                g2v[a] = Gr[uu[a] + U];
                gsv[a] = Gr[uu[a] + 2 * U];
            }
        }
        if (mv) {
            ull acc[2][NP][2];
#pragma unroll
            for (int b = 0; b < 2; ++b)
#pragma unroll
                for (int p = 0; p < NP; ++p) { acc[b][p][0] = 0ull; acc[b][p][1] = 0ull; }
#pragma unroll
            for (int j = 0; j < KR; j += 2) {
                ulonglong2 h0 = *(const ulonglong2*)&shd[0 * UP + kbase + j];
                ulonglong2 h1 = *(const ulonglong2*)&shd[1 * UP + kbase + j];
#pragma unroll
                for (int p = 0; p < NP; ++p) {
                    acc[0][p][0] = ffma2(w[j * NP + p],       h0.x, acc[0][p][0]);
                    acc[0][p][1] = ffma2(w[(j + 1) * NP + p], h0.y, acc[0][p][1]);
                    acc[1][p][0] = ffma2(w[j * NP + p],       h1.x, acc[1][p][0]);
                    acc[1][p][1] = ffma2(w[(j + 1) * NP + p], h1.y, acc[1][p][1]);
                }
            }
#pragma unroll
            for (int j = 0; j < KS; j += 2) {
                ulonglong2 h0 = *(const ulonglong2*)&shd[0 * UP + kbase + KR + j];
                ulonglong2 h1 = *(const ulonglong2*)&shd[1 * UP + kbase + KR + j];
#pragma unroll
                for (int p = 0; p < NP; ++p) {
                    ull wa = sW[((j)     * NP + p) * MT + tid];
                    ull wb = sW[((j + 1) * NP + p) * MT + tid];
                    acc[0][p][0] = ffma2(wa, h0.x, acc[0][p][0]);
                    acc[0][p][1] = ffma2(wb, h0.y, acc[0][p][1]);
                    acc[1][p][0] = ffma2(wa, h1.x, acc[1][p][0]);
                    acc[1][p][1] = ffma2(wb, h1.y, acc[1][p][1]);
                }
            }
#pragma unroll
            for (int b = 0; b < 2; ++b)
#pragma unroll
                for (int p = 0; p < NP; ++p) {
                    float2 f = funpack(fadd2(acc[b][p][0], acc[b][p][1]));
                    *(float2*)&sgp[(s * 2 + b) * NGP + n0 + 2 * p] = f;
                }
        }
        __syncthreads();
#pragma unroll
        for (int a = 0; a < NACT; ++a) {
            if (uvalid[a]) {
                int bb = ubb[a], u = uu[a];
                float x1 = g1v[a], x2 = g2v[a], xs = gsv[a];
#pragma unroll
                for (int s2 = 0; s2 < NSPLIT; ++s2) {
                    const float* row = &sgp[(s2 * 2 + bb) * NGP];
                    x1 += row[u];
                    x2 += row[u + U];
                    xs += row[u + 2 * U];
                }
                float f1 = tanhf(x1), f2 = tanhf(x2);
                float sig = 1.f / (1.f + __expf(-xs));
                float hn = f1 + sig * (f2 - f1);
                Hp[((size_t)bb * TSTEPS + t) * UP + u] = hn;
                shd[bb * UP + u] = fdup(hn);
            }
        }
        __syncthreads();
    }
}

// rec configs (unchanged)
#define R0_TN 4
#define R0_NS 2
#define R0_KR 40
#define R0_TH 256
#define R1_TN 2
#define R1_NS 2
#define R1_KR 48
#define R1_TH 288
#define R2_TN 2
#define R2_NS 1
#define R2_KR 32
#define R2_TH 96

static size_t rec_sm2(int NGP, int UP, int TN, int NSPLIT, int KR) {
    int NP = TN / 2, P = NGP / TN;
    int KH = UP / NSPLIT, KS = KH - KR;
    int MT = P * NSPLIT;
    size_t swn = (size_t)KS * NP * MT;
    return (swn + 2 * (size_t)UP) * 8 + (size_t)NSPLIT * 2 * NGP * 4;
}

// ---------------------------------------------------------------------------
// host side
// ---------------------------------------------------------------------------
static float* dev_addr(const void* sym) {
    void* p = nullptr;
    cudaGetSymbolAddress(&p, sym);
    return (float*)p;
}

extern "C" void kernel_launch(void* const* d_in, const int* in_sizes, int n_in,
                              void* d_out, int out_size) {
    // Resolve input ordering: dict order has mask0 (35505 ints) at index 9,
    // signature order has l1_ff1_w (19936 floats) there.
    int L0 = 1, M0, L1, M1, L2, M2, FCW, FCB;
    if (in_sizes[9] == 19936) {            // signature order
        L1 = 9; L2 = 17; FCW = 25; FCB = 26; M0 = 27; M1 = 28; M2 = 29;
    } else {                               // dict order
        M0 = 9; L1 = 10; M1 = 18; L2 = 19; M2 = 27; FCW = 28; FCB = 29;
    }

    const float* X = (const float*)d_in[0];
    float* OUT = (float*)d_out;

    float* G0 = dev_addr(g_G0); float* H0 = dev_addr(g_H0);
    float* G1 = dev_addr(g_G1); float* H1 = dev_addr(g_H1);
    float* G2 = dev_addr(g_G2); float* H2 = dev_addr(g_H2);
    float* Wx0 = dev_addr(g_Wx0); float* Wh0 = dev_addr(g_Wh0); float* B0 = dev_addr(g_b0);
    float* Wx1 = dev_addr(g_Wx1); float* Wh1 = dev_addr(g_Wh1); float* B1 = dev_addr(g_b1);
    float* Wx2 = dev_addr(g_Wx2); float* Wh2 = dev_addr(g_Wh2); float* B2 = dev_addr(g_b2);
    float* FcT = dev_addr(g_fcwT);

    size_t sm0 = rec_sm2(NGP0, UP0, R0_TN, R0_NS, R0_KR);
    size_t sm1 = rec_sm2(NGP1, UP1, R1_TN, R1_NS, R1_KR);
    size_t sm2 = rec_sm2(NGP2, UP2, R2_TN, R2_NS, R2_KR);
    cudaFuncSetAttribute((const void*)rec_hyb2<U0, UP0, NGP0, R0_TN, R0_NS, R0_KR, R0_TH>,
                         cudaFuncAttributeMaxDynamicSharedMemorySize, (int)sm0);
    cudaFuncSetAttribute((const void*)rec_hyb2<U1, UP1, NGP1, R1_TN, R1_NS, R1_KR, R1_TH>,
                         cudaFuncAttributeMaxDynamicSharedMemorySize, (int)sm1);
    cudaFuncSetAttribute((const void*)rec_hyb2<U2, UP2, NGP2, R2_TN, R2_NS, R2_KR, R2_TH>,
                         cudaFuncAttributeMaxDynamicSharedMemorySize, (int)sm2);

    // ---- fused weight prep (1 launch) ----
    prep_all<<<512, 256>>>(
        (const float*)d_in[L0 + 0], (const float*)d_in[L0 + 1],
        (const float*)d_in[L0 + 2], (const float*)d_in[L0 + 3],
        (const float*)d_in[L0 + 4], (const float*)d_in[L0 + 5],
        (const float*)d_in[L0 + 6], (const float*)d_in[L0 + 7],
        (const int*)d_in[M0],
        (const float*)d_in[L1 + 0], (const float*)d_in[L1 + 1],
        (const float*)d_in[L1 + 2], (const float*)d_in[L1 + 3],
        (const float*)d_in[L1 + 4], (const float*)d_in[L1 + 5],
        (const float*)d_in[L1 + 6], (const float*)d_in[L1 + 7],
        (const int*)d_in[M1],
        (const float*)d_in[L2 + 0], (const float*)d_in[L2 + 1],
        (const float*)d_in[L2 + 2], (const float*)d_in[L2 + 3],
        (const float*)d_in[L2 + 4], (const float*)d_in[L2 + 5],
        (const float*)d_in[L2 + 6], (const float*)d_in[L2 + 7],
        (const int*)d_in[M2],
        (const float*)d_in[FCW],
        Wx0, Wh0, B0, Wx1, Wh1, B1, Wx2, Wh2, B2, FcT);

    const int MBB = MROWS / 128;   // 2048

    // ---- layer 0 ----
    gemm_bias4<<<dim3((NGP0 + 63) / 64, MBB), 128>>>(X, FIN0, Wx0, NGP0, B0, G0, NGP0, NGP0, FIN0);
    rec_hyb2<U0, UP0, NGP0, R0_TN, R0_NS, R0_KR, R0_TH>
        <<<NBATCH / 2, R0_TH, sm0>>>(G0, Wh0, H0);
    // ---- layer 1 ----
    gemm_bias4<<<dim3((NGP1 + 63) / 64, MBB), 128>>>(H0, UP0, Wx1, NGP1, B1, G1, NGP1, NGP1, U0);
    rec_hyb2<U1, UP1, NGP1, R1_TN, R1_NS, R1_KR, R1_TH>
        <<<NBATCH / 2, R1_TH, sm1>>>(G1, Wh1, H1);
    // ---- layer 2 ----
    gemm_bias4<<<dim3((NGP2 + 63) / 64, MBB), 128>>>(H1, UP1, Wx2, NGP2, B2, G2, NGP2, NGP2, U1);
    rec_hyb2<U2, UP2, NGP2, R2_TN, R2_NS, R2_KR, R2_TH>
        <<<NBATCH / 2, R2_TH, sm2>>>(G2, Wh2, H2);
    // ---- final FC (adaptive pool is identity since MOT == OUT) ----
    gemm_bias4<<<dim3(1, MBB), 128>>>(H2, UP2, FcT, 32, (const float*)d_in[FCB], OUT, 32, 32, 32);
}

// round 15
// speedup vs baseline: 1.7629x; 1.0195x over previous
#include <cuda_runtime.h>
#include <cuda_bf16.h>
#include <cstdint>
#include <cstddef>

// ---------------------------------------------------------------------------
// LiquidNeuralNetwork (CfC / AutoNCP) — R15
//  * GEMM: gemm_bias4 unchanged (R12 4430us pass; crossbar/FMA balanced)
//  * rec:  rec_hyb3 — fast-exact activations (__expf + __fdividef; no
//    libdevice tanhf / IEEE div) and paired SMEM weight layout (LDS.128).
// ---------------------------------------------------------------------------

typedef unsigned long long ull;

#define TSTEPS 1024
#define NBATCH 256
#define MROWS  (NBATCH * TSTEPS)

// layer dims
#define U0 135
#define FIN0 128
#define NG0 405
#define NGP0 408
#define UP0 136

#define U1 89
#define FIN1 135
#define NG1 267
#define NGP1 272
#define UP1 96

#define U2 32
#define FIN2 89
#define NG2 96
#define NGP2 96
#define UP2 32

// ---------------- f32x2 helpers (ptxas won't auto-fuse; inline PTX) --------
__device__ __forceinline__ ull ffma2(ull a, ull b, ull c) {
    ull d; asm("fma.rn.f32x2 %0, %1, %2, %3;" : "=l"(d) : "l"(a), "l"(b), "l"(c));
    return d;
}
__device__ __forceinline__ ull fadd2(ull a, ull b) {
    ull d; asm("add.rn.f32x2 %0, %1, %2;" : "=l"(d) : "l"(a), "l"(b));
    return d;
}
__device__ __forceinline__ ull fdup(float x) {
    ull d; asm("mov.b64 %0, {%1, %1};" : "=l"(d) : "f"(x));
    return d;
}
__device__ __forceinline__ ull fpack(float lo, float hi) {
    ull d; asm("mov.b64 %0, {%1, %2};" : "=l"(d) : "f"(lo), "f"(hi));
    return d;
}
__device__ __forceinline__ float2 funpack(ull v) {
    float2 f; asm("mov.b64 {%0, %1}, %2;" : "=f"(f.x), "=f"(f.y) : "l"(v));
    return f;
}

// fast-exact tanh: (e^{2x}-1)/(e^{2x}+1); clamp keeps e^{2x} finite.
// __expf / __fdividef are ~2-ulp MUFU paths -> error ~1e-6, vs 1e-3 budget.
__device__ __forceinline__ float ftanh(float x) {
    float xc = fminf(fmaxf(x, -15.f), 15.f);
    float e = __expf(2.f * xc);
    return __fdividef(e - 1.f, e + 1.f);
}
__device__ __forceinline__ float fsig(float x) {
    return __fdividef(1.f, 1.f + __expf(-x));
}

// ---------------- scratch (device globals; zero-initialized) ---------------
__device__ float g_G0[(size_t)MROWS * NGP0];
__device__ float g_H0[(size_t)MROWS * UP0];
__device__ float g_G1[(size_t)MROWS * NGP1];
__device__ float g_H1[(size_t)MROWS * UP1];
__device__ float g_G2[(size_t)MROWS * NGP2];
__device__ float g_H2[(size_t)MROWS * UP2];

__device__ float g_Wx0[FIN0 * NGP0];
__device__ float g_Wh0[UP0 * NGP0];
__device__ float g_b0[NGP0];
__device__ float g_Wx1[FIN1 * NGP1];
__device__ float g_Wh1[UP1 * NGP1];
__device__ float g_b1[NGP1];
__device__ float g_Wx2[FIN2 * NGP2];
__device__ float g_Wh2[UP2 * NGP2];
__device__ float g_b2[NGP2];
__device__ float g_fcwT[32 * 32];

// ---------------------------------------------------------------------------
// Fused weight prep (unchanged).
// Gate order n: [0,U)=ff1, [U,2U)=ff2, [2U,3U)=s(=ta+tb merged).
// ---------------------------------------------------------------------------
__device__ __forceinline__ void prep_dev(
    int U, int FIN, int NG, int NGP, int UP,
    const float* __restrict__ ff1w, const float* __restrict__ ff1b,
    const float* __restrict__ ff2w, const float* __restrict__ ff2b,
    const float* __restrict__ taw,  const float* __restrict__ tab,
    const float* __restrict__ tbw,  const float* __restrict__ tbb,
    const int*   __restrict__ mask,
    float* __restrict__ Wx, float* __restrict__ Wh, float* __restrict__ bias,
    int g0, int stride)
{
    const int C = FIN + U;
    for (int i = g0; i < FIN * NGP; i += stride) {
        int k = i / NGP, n = i % NGP;
        float v = 0.f;
        if (n < U)          v = ff1w[n * C + k] * (float)mask[n * C + k];
        else if (n < 2 * U) v = ff2w[(n - U) * C + k] * (float)mask[(n - U) * C + k];
        else if (n < NG)    v = taw[(n - 2 * U) * C + k] + tbw[(n - 2 * U) * C + k];
        Wx[i] = v;
    }
    for (int i = g0; i < UP * NGP; i += stride) {
        int k = i / NGP, n = i % NGP;
        float v = 0.f;
        if (k < U) {   // recurrent block of the NCP mask is all-ones
            if (n < U)          v = ff1w[n * C + FIN + k];
            else if (n < 2 * U) v = ff2w[(n - U) * C + FIN + k];
            else if (n < NG)    v = taw[(n - 2 * U) * C + FIN + k] + tbw[(n - 2 * U) * C + FIN + k];
        }
        Wh[i] = v;
    }
    for (int i = g0; i < NGP; i += stride) {
        float v = 0.f;
        if (i < U)          v = ff1b[i];
        else if (i < 2 * U) v = ff2b[i - U];
        else if (i < NG)    v = tab[i - 2 * U] + tbb[i - 2 * U];
        bias[i] = v;
    }
}

__global__ void prep_all(
    const float* f1w0, const float* f1b0, const float* f2w0, const float* f2b0,
    const float* taw0, const float* tab0, const float* tbw0, const float* tbb0,
    const int* m0,
    const float* f1w1, const float* f1b1, const float* f2w1, const float* f2b1,
    const float* taw1, const float* tab1, const float* tbw1, const float* tbb1,
    const int* m1,
    const float* f1w2, const float* f1b2, const float* f2w2, const float* f2b2,
    const float* taw2, const float* tab2, const float* tbw2, const float* tbb2,
    const int* m2,
    const float* fcw,
    float* Wx0, float* Wh0, float* B0,
    float* Wx1, float* Wh1, float* B1,
    float* Wx2, float* Wh2, float* B2,
    float* fcT)
{
    int g0 = blockIdx.x * blockDim.x + threadIdx.x;
    int st = gridDim.x * blockDim.x;
    prep_dev(U0, FIN0, NG0, NGP0, UP0, f1w0, f1b0, f2w0, f2b0, taw0, tab0, tbw0, tbb0,
             m0, Wx0, Wh0, B0, g0, st);
    prep_dev(U1, FIN1, NG1, NGP1, UP1, f1w1, f1b1, f2w1, f2b1, taw1, tab1, tbw1, tbb1,
             m1, Wx1, Wh1, B1, g0, st);
    prep_dev(U2, FIN2, NG2, NGP2, UP2, f1w2, f1b2, f2w2, f2b2, taw2, tab2, tbw2, tbb2,
             m2, Wx2, Wh2, B2, g0, st);
    if (g0 < 1024) {
        int o = g0 >> 5, k = g0 & 31;
        fcT[k * 32 + o] = fcw[o * 32 + k];
    }
}

// ---------------------------------------------------------------------------
// GEMM + bias, f32x2. BM=128, BN=64, BK=16, 128 threads, 8m x 8n microtile.
// (unchanged from R12 4430us pass)
// ---------------------------------------------------------------------------
__global__ __launch_bounds__(128)
void gemm_bias4(const float* __restrict__ A, int lda,
                const float* __restrict__ Bt, int ldb,
                const float* __restrict__ bias,
                float* __restrict__ C, int ldc,
                int N, int K) {
    __shared__ float sA[16][128];   // [k][m]
    __shared__ float sB[16][64];    // [k][n]
    const int bm = blockIdx.y * 128;
    const int bn = blockIdx.x * 64;
    const int tid = threadIdx.x;
    const int tm = (tid >> 3) << 3;
    const int tn = (tid & 7) << 3;

    ull acc[8][4];
#pragma unroll
    for (int r = 0; r < 8; ++r)
#pragma unroll
        for (int p = 0; p < 4; ++p) acc[r][p] = 0ull;

    for (int k0 = 0; k0 < K; k0 += 16) {
#pragma unroll
        for (int i = 0; i < 4; ++i) {
            int e = tid + i * 128;
            int m = e & 127;
            int k4 = (e >> 7) << 2;
            const float* src = A + (size_t)(bm + m) * lda + k0 + k4;
            float4 v;
            if (k0 + k4 + 3 < K) {
                v = *(const float4*)src;
            } else {
                v.x = (k0 + k4     < K) ? src[0] : 0.f;
                v.y = (k0 + k4 + 1 < K) ? src[1] : 0.f;
                v.z = (k0 + k4 + 2 < K) ? src[2] : 0.f;
                v.w = 0.f;
            }
            sA[k4 + 0][m] = v.x;
            sA[k4 + 1][m] = v.y;
            sA[k4 + 2][m] = v.z;
            sA[k4 + 3][m] = v.w;
        }
#pragma unroll
        for (int i = 0; i < 2; ++i) {
            int e = tid + i * 128;
            int kk = e >> 4;
            int n4 = (e & 15) << 2;
            float4 v = make_float4(0.f, 0.f, 0.f, 0.f);
            if (k0 + kk < K && bn + n4 < N)
                v = *(const float4*)&Bt[(size_t)(k0 + kk) * ldb + bn + n4];
            *(float4*)&sB[kk][n4] = v;
        }
        __syncthreads();
#pragma unroll
        for (int kk = 0; kk < 16; ++kk) {
            float4 a0 = *(const float4*)&sA[kk][tm];
            float4 a1 = *(const float4*)&sA[kk][tm + 4];
            ulonglong2 b0 = *(const ulonglong2*)&sB[kk][tn];
            ulonglong2 b1 = *(const ulonglong2*)&sB[kk][tn + 4];
            ull bb[4] = {b0.x, b0.y, b1.x, b1.y};
            ull d[8];
            d[0] = fdup(a0.x); d[1] = fdup(a0.y);
            d[2] = fdup(a0.z); d[3] = fdup(a0.w);
            d[4] = fdup(a1.x); d[5] = fdup(a1.y);
            d[6] = fdup(a1.z); d[7] = fdup(a1.w);
#pragma unroll
            for (int r = 0; r < 8; ++r)
#pragma unroll
                for (int p = 0; p < 4; ++p)
                    acc[r][p] = ffma2(d[r], bb[p], acc[r][p]);
        }
        __syncthreads();
    }
#pragma unroll
    for (int r = 0; r < 8; ++r) {
        float* crow = C + (size_t)(bm + tm + r) * ldc + bn + tn;
#pragma unroll
        for (int p = 0; p < 4; ++p) {
            int n = bn + tn + 2 * p;
            if (n < N) {
                float2 f = funpack(acc[r][p]);
                f.x += bias[n];
                f.y += bias[n + 1];
                *(float2*)(crow + 2 * p) = f;
            }
        }
    }
}

// ---------------------------------------------------------------------------
// Recurrent pass v3.
//  * Paired SMEM weight layout [j/2][p][MT][2] -> conflict-free LDS.128
//    (halves SMEM-weight load count vs v2). KS is even for all configs.
//  * Fast-exact activations (ftanh/fsig, MUFU-based, ~1e-6 error).
//  * Otherwise identical to rec_hyb2 (R11/R12 pass).
// ---------------------------------------------------------------------------
template<int U, int UP, int NGP, int TN, int NSPLIT, int KR, int THREADS>
__global__ __launch_bounds__(THREADS, 1)
void rec_hyb3(const float* __restrict__ G, const float* __restrict__ Wg,
              float* __restrict__ H) {
    constexpr int NP = TN / 2;
    constexpr int P = NGP / TN;
    constexpr int KH = UP / NSPLIT;
    constexpr int KS = KH - KR;
    static_assert(KS % 2 == 0, "paired layout needs even KS");
    constexpr int MT = P * NSPLIT;
    constexpr int SWN = KS * NP * MT;
    constexpr int NACT = (2 * U + THREADS - 1) / THREADS;

    extern __shared__ __align__(16) unsigned char dynsmem[];
    ull* sW   = (ull*)dynsmem;                   // [KS/2][NP][MT][2]
    ull* shd  = sW + SWN;                        // [2][UP] dup'd h
    float* sgp = (float*)(shd + 2 * UP);         // [NSPLIT][2][NGP]

    const int tid = threadIdx.x;
    const bool mv = tid < MT;
    const int s = mv ? (tid / P) : 0;
    const int cg = tid % P;
    const int n0 = cg * TN;
    const int kbase = s * KH;

    ull w[KR * NP];
#pragma unroll
    for (int j = 0; j < KR; ++j)
#pragma unroll
        for (int p = 0; p < NP; ++p) {
            float2 wv = *(const float2*)&Wg[(size_t)(kbase + j) * NGP + n0 + 2 * p];
            w[j * NP + p] = fpack(wv.x, wv.y);
        }
    // paired SMEM weights: idx = ((j/2)*NP + p)*2*MT + 2*m + (j&1)
    for (int idx = tid; idx < SWN; idx += THREADS) {
        int q2 = idx / (2 * MT);
        int r  = idx % (2 * MT);
        int m  = r >> 1;
        int par = r & 1;
        int j = (q2 / NP) * 2 + par;
        int p = q2 % NP;
        int sm_ = m / P, cgm = m % P;
        float2 wv = *(const float2*)&Wg[(size_t)(sm_ * KH + KR + j) * NGP + cgm * TN + 2 * p];
        sW[idx] = fpack(wv.x, wv.y);
    }
    for (int i = tid; i < 2 * UP; i += THREADS) shd[i] = 0ull;
    __syncthreads();

    const size_t bb0 = (size_t)blockIdx.x * 2;
    const float* Gbase = G + bb0 * TSTEPS * NGP;
    const size_t GOFF = (size_t)TSTEPS * NGP;
    float* Hp = H + bb0 * TSTEPS * UP;

    int ubb[NACT], uu[NACT];
    bool uvalid[NACT];
#pragma unroll
    for (int a = 0; a < NACT; ++a) {
        int i = tid + a * THREADS;
        uvalid[a] = (i < 2 * U);
        ubb[a] = (i >= U) ? 1 : 0;
        uu[a] = i - ubb[a] * U;
    }

    for (int t = 0; t < TSTEPS; ++t) {
        float g1v[NACT], g2v[NACT], gsv[NACT];
#pragma unroll
        for (int a = 0; a < NACT; ++a) {
            if (uvalid[a]) {
                const float* Gr = Gbase + (ubb[a] ? GOFF : 0) + (size_t)t * NGP;
                g1v[a] = Gr[uu[a]];
                g2v[a] = Gr[uu[a] + U];
                gsv[a] = Gr[uu[a] + 2 * U];
            }
        }
        if (mv) {
            ull acc[2][NP][2];
#pragma unroll
            for (int b = 0; b < 2; ++b)
#pragma unroll
                for (int p = 0; p < NP; ++p) { acc[b][p][0] = 0ull; acc[b][p][1] = 0ull; }
#pragma unroll
            for (int j = 0; j < KR; j += 2) {          // register weights
                ulonglong2 h0 = *(const ulonglong2*)&shd[0 * UP + kbase + j];
                ulonglong2 h1 = *(const ulonglong2*)&shd[1 * UP + kbase + j];
#pragma unroll
                for (int p = 0; p < NP; ++p) {
                    acc[0][p][0] = ffma2(w[j * NP + p],       h0.x, acc[0][p][0]);
                    acc[0][p][1] = ffma2(w[(j + 1) * NP + p], h0.y, acc[0][p][1]);
                    acc[1][p][0] = ffma2(w[j * NP + p],       h1.x, acc[1][p][0]);
                    acc[1][p][1] = ffma2(w[(j + 1) * NP + p], h1.y, acc[1][p][1]);
                }
            }
#pragma unroll
            for (int j2 = 0; j2 < KS / 2; ++j2) {      // SMEM weights, LDS.128
                int j = 2 * j2;
                ulonglong2 h0 = *(const ulonglong2*)&shd[0 * UP + kbase + KR + j];
                ulonglong2 h1 = *(const ulonglong2*)&shd[1 * UP + kbase + KR + j];
#pragma unroll
                for (int p = 0; p < NP; ++p) {
                    ulonglong2 wp = *(const ulonglong2*)&sW[((size_t)(j2 * NP + p) * 2) * MT + 2 * tid];
                    acc[0][p][0] = ffma2(wp.x, h0.x, acc[0][p][0]);
                    acc[0][p][1] = ffma2(wp.y, h0.y, acc[0][p][1]);
                    acc[1][p][0] = ffma2(wp.x, h1.x, acc[1][p][0]);
                    acc[1][p][1] = ffma2(wp.y, h1.y, acc[1][p][1]);
                }
            }
#pragma unroll
            for (int b = 0; b < 2; ++b)
#pragma unroll
                for (int p = 0; p < NP; ++p) {
                    float2 f = funpack(fadd2(acc[b][p][0], acc[b][p][1]));
                    *(float2*)&sgp[(s * 2 + b) * NGP + n0 + 2 * p] = f;
                }
        }
        __syncthreads();
#pragma unroll
        for (int a = 0; a < NACT; ++a) {
            if (uvalid[a]) {
                int bb = ubb[a], u = uu[a];
                float x1 = g1v[a], x2 = g2v[a], xs = gsv[a];
#pragma unroll
                for (int s2 = 0; s2 < NSPLIT; ++s2) {
                    const float* row = &sgp[(s2 * 2 + bb) * NGP];
                    x1 += row[u];
                    x2 += row[u + U];
                    xs += row[u + 2 * U];
                }
                float f1 = ftanh(x1), f2 = ftanh(x2);
                float sig = fsig(xs);
                float hn = f1 + sig * (f2 - f1);
                Hp[((size_t)bb * TSTEPS + t) * UP + u] = hn;
                shd[bb * UP + u] = fdup(hn);
            }
        }
        __syncthreads();
    }
}

// rec configs (unchanged)
#define R0_TN 4
#define R0_NS 2
#define R0_KR 40
#define R0_TH 256
#define R1_TN 2
#define R1_NS 2
#define R1_KR 48
#define R1_TH 288
#define R2_TN 2
#define R2_NS 1
#define R2_KR 32
#define R2_TH 96

static size_t rec_sm2(int NGP, int UP, int TN, int NSPLIT, int KR) {
    int NP = TN / 2, P = NGP / TN;
    int KH = UP / NSPLIT, KS = KH - KR;
    int MT = P * NSPLIT;
    size_t swn = (size_t)KS * NP * MT;
    return (swn + 2 * (size_t)UP) * 8 + (size_t)NSPLIT * 2 * NGP * 4;
}

// ---------------------------------------------------------------------------
// host side
// ---------------------------------------------------------------------------
static float* dev_addr(const void* sym) {
    void* p = nullptr;
    cudaGetSymbolAddress(&p, sym);
    return (float*)p;
}

extern "C" void kernel_launch(void* const* d_in, const int* in_sizes, int n_in,
                              void* d_out, int out_size) {
    // Resolve input ordering: dict order has mask0 (35505 ints) at index 9,
    // signature order has l1_ff1_w (19936 floats) there.
    int L0 = 1, M0, L1, M1, L2, M2, FCW, FCB;
    if (in_sizes[9] == 19936) {            // signature order
        L1 = 9; L2 = 17; FCW = 25; FCB = 26; M0 = 27; M1 = 28; M2 = 29;
    } else {                               // dict order
        M0 = 9; L1 = 10; M1 = 18; L2 = 19; M2 = 27; FCW = 28; FCB = 29;
    }

    const float* X = (const float*)d_in[0];
    float* OUT = (float*)d_out;

    float* G0 = dev_addr(g_G0); float* H0 = dev_addr(g_H0);
    float* G1 = dev_addr(g_G1); float* H1 = dev_addr(g_H1);
    float* G2 = dev_addr(g_G2); float* H2 = dev_addr(g_H2);
    float* Wx0 = dev_addr(g_Wx0); float* Wh0 = dev_addr(g_Wh0); float* B0 = dev_addr(g_b0);
    float* Wx1 = dev_addr(g_Wx1); float* Wh1 = dev_addr(g_Wh1); float* B1 = dev_addr(g_b1);
    float* Wx2 = dev_addr(g_Wx2); float* Wh2 = dev_addr(g_Wh2); float* B2 = dev_addr(g_b2);
    float* FcT = dev_addr(g_fcwT);

    size_t sm0 = rec_sm2(NGP0, UP0, R0_TN, R0_NS, R0_KR);
    size_t sm1 = rec_sm2(NGP1, UP1, R1_TN, R1_NS, R1_KR);
    size_t sm2 = rec_sm2(NGP2, UP2, R2_TN, R2_NS, R2_KR);
    cudaFuncSetAttribute((const void*)rec_hyb3<U0, UP0, NGP0, R0_TN, R0_NS, R0_KR, R0_TH>,
                         cudaFuncAttributeMaxDynamicSharedMemorySize, (int)sm0);
    cudaFuncSetAttribute((const void*)rec_hyb3<U1, UP1, NGP1, R1_TN, R1_NS, R1_KR, R1_TH>,
                         cudaFuncAttributeMaxDynamicSharedMemorySize, (int)sm1);
    cudaFuncSetAttribute((const void*)rec_hyb3<U2, UP2, NGP2, R2_TN, R2_NS, R2_KR, R2_TH>,
                         cudaFuncAttributeMaxDynamicSharedMemorySize, (int)sm2);

    // ---- fused weight prep (1 launch) ----
    prep_all<<<512, 256>>>(
        (const float*)d_in[L0 + 0], (const float*)d_in[L0 + 1],
        (const float*)d_in[L0 + 2], (const float*)d_in[L0 + 3],
        (const float*)d_in[L0 + 4], (const float*)d_in[L0 + 5],
        (const float*)d_in[L0 + 6], (const float*)d_in[L0 + 7],
        (const int*)d_in[M0],
        (const float*)d_in[L1 + 0], (const float*)d_in[L1 + 1],
        (const float*)d_in[L1 + 2], (const float*)d_in[L1 + 3],
        (const float*)d_in[L1 + 4], (const float*)d_in[L1 + 5],
        (const float*)d_in[L1 + 6], (const float*)d_in[L1 + 7],
        (const int*)d_in[M1],
        (const float*)d_in[L2 + 0], (const float*)d_in[L2 + 1],
        (const float*)d_in[L2 + 2], (const float*)d_in[L2 + 3],
        (const float*)d_in[L2 + 4], (const float*)d_in[L2 + 5],
        (const float*)d_in[L2 + 6], (const float*)d_in[L2 + 7],
        (const int*)d_in[M2],
        (const float*)d_in[FCW],
        Wx0, Wh0, B0, Wx1, Wh1, B1, Wx2, Wh2, B2, FcT);

    const int MBB = MROWS / 128;   // 2048

    // ---- layer 0 ----
    gemm_bias4<<<dim3((NGP0 + 63) / 64, MBB), 128>>>(X, FIN0, Wx0, NGP0, B0, G0, NGP0, NGP0, FIN0);
    rec_hyb3<U0, UP0, NGP0, R0_TN, R0_NS, R0_KR, R0_TH>
        <<<NBATCH / 2, R0_TH, sm0>>>(G0, Wh0, H0);
    // ---- layer 1 ----
    gemm_bias4<<<dim3((NGP1 + 63) / 64, MBB), 128>>>(H0, UP0, Wx1, NGP1, B1, G1, NGP1, NGP1, U0);
    rec_hyb3<U1, UP1, NGP1, R1_TN, R1_NS, R1_KR, R1_TH>
        <<<NBATCH / 2, R1_TH, sm1>>>(G1, Wh1, H1);
    // ---- layer 2 ----
    gemm_bias4<<<dim3((NGP2 + 63) / 64, MBB), 128>>>(H1, UP1, Wx2, NGP2, B2, G2, NGP2, NGP2, U1);
    rec_hyb3<U2, UP2, NGP2, R2_TN, R2_NS, R2_KR, R2_TH>
        <<<NBATCH / 2, R2_TH, sm2>>>(G2, Wh2, H2);
    // ---- final FC (adaptive pool is identity since MOT == OUT) ----
    gemm_bias4<<<dim3(1, MBB), 128>>>(H2, UP2, FcT, 32, (const float*)d_in[FCB], OUT, 32, 32, 32);
}